// round 6
// baseline (speedup 1.0000x reference)
#include <cuda_runtime.h>
#include <math_constants.h>

#define Bb 4
#define Pp 8192
#define Cc 64
#define Mm 2048
#define NB 64
#define OUTC 384

// scratch (allocation-free rule: __device__ globals)
__device__ int   g_nn_idx[Bb*Mm*NB];
__device__ float g_nn_d2 [Bb*Mm*NB];

// ---------------- packed f32x2 helpers (bitwise == two scalar rn ops) -------
typedef unsigned long long u64;

__device__ __forceinline__ u64 pk2(float lo, float hi) {
    u64 r; asm("mov.b64 %0, {%1, %2};" : "=l"(r) : "f"(lo), "f"(hi)); return r;
}
__device__ __forceinline__ void upk2(float& lo, float& hi, u64 v) {
    asm("mov.b64 {%0, %1}, %2;" : "=f"(lo), "=f"(hi) : "l"(v));
}
__device__ __forceinline__ u64 add2(u64 a, u64 b) {
    u64 d; asm("add.rn.f32x2 %0, %1, %2;" : "=l"(d) : "l"(a), "l"(b)); return d;
}
__device__ __forceinline__ u64 mul2(u64 a, u64 b) {
    u64 d; asm("mul.rn.f32x2 %0, %1, %2;" : "=l"(d) : "l"(a), "l"(b)); return d;
}
__device__ __forceinline__ u64 fma2(u64 a, u64 b, u64 c) {
    u64 d; asm("fma.rn.f32x2 %0, %1, %2, %3;" : "=l"(d) : "l"(a), "l"(b), "l"(c)); return d;
}

// ---------------------------------------------------------------------------
// Kernel 1: farthest point sampling, one block per batch.
// Bitwise-identical selection to the JAX scan: ((dx*dx+dy*dy)+dz*dz) rn ops,
// no fma contraction; argmax ties -> lowest index.
// Single barrier per iteration: warp REDUX -> leaders write double-buffered
// smem -> bar -> every warp re-reduces the 32 leader values itself.
// ---------------------------------------------------------------------------
__global__ void __launch_bounds__(1024) fps_kernel(const float* __restrict__ pos,
                                                   float* __restrict__ pos_s)
{
    const int b = blockIdx.x;
    const float* pb = pos + (size_t)b * Pp * 3;
    float* ps = pos_s + (size_t)b * Mm * 3;
    const int tid = threadIdx.x;
    const int lane = tid & 31, wrp = tid >> 5;

    u64 px2[4], py2[4], pz2[4];
    unsigned mind[8];
#pragma unroll
    for (int q = 0; q < 4; q++) {
        int p0 = tid + (2 * q) * 1024;
        int p1 = tid + (2 * q + 1) * 1024;
        px2[q] = pk2(pb[3 * p0],     pb[3 * p1]);
        py2[q] = pk2(pb[3 * p0 + 1], pb[3 * p1 + 1]);
        pz2[q] = pk2(pb[3 * p0 + 2], pb[3 * p1 + 2]);
    }
#pragma unroll
    for (int i = 0; i < 8; i++) mind[i] = __float_as_uint(1e30f);

    __shared__ unsigned swv[2][32];
    __shared__ unsigned swi[2][32];

    unsigned sel = 0;
    for (int t = 0; t < Mm; t++) {
        float lx = pb[3 * sel], ly = pb[3 * sel + 1], lz = pb[3 * sel + 2];
        if (tid == 0) { ps[3 * t] = lx; ps[3 * t + 1] = ly; ps[3 * t + 2] = lz; }

        u64 nx2 = pk2(-lx, -lx);
        u64 ny2 = pk2(-ly, -ly);
        u64 nz2 = pk2(-lz, -lz);

#pragma unroll
        for (int q = 0; q < 4; q++) {
            u64 dx = add2(px2[q], nx2);
            u64 dy = add2(py2[q], ny2);
            u64 dz = add2(pz2[q], nz2);
            u64 s  = add2(add2(mul2(dx, dx), mul2(dy, dy)), mul2(dz, dz));
            float dlo, dhi;
            upk2(dlo, dhi, s);
            mind[2 * q]     = min(mind[2 * q],     __float_as_uint(dlo));
            mind[2 * q + 1] = min(mind[2 * q + 1], __float_as_uint(dhi));
        }
        // 7-op max tree (d2 >= 0 -> uint order == float order)
        unsigned m01 = max(mind[0], mind[1]), m23 = max(mind[2], mind[3]);
        unsigned m45 = max(mind[4], mind[5]), m67 = max(mind[6], mind[7]);
        unsigned bv  = max(max(m01, m23), max(m45, m67));

        // warp argmax (value first, then lowest point index among matches)
        unsigned wv = __reduce_max_sync(0xffffffffu, bv);
        unsigned cand = 0xffffffffu;
        if (bv == wv) {
#pragma unroll
            for (int i = 7; i >= 0; i--)
                if (mind[i] == wv) cand = (unsigned)(tid + (i << 10));
        }
        unsigned wi = __reduce_min_sync(0xffffffffu, cand);

        const int buf = t & 1;
        if (lane == 0) { swv[buf][wrp] = wv; swi[buf][wrp] = wi; }
        __syncthreads();

        // every warp resolves the block winner itself (no 2nd barrier)
        unsigned v  = swv[buf][lane];
        unsigned ii = swi[buf][lane];
        unsigned gv = __reduce_max_sync(0xffffffffu, v);
        unsigned c2 = (v == gv) ? ii : 0xffffffffu;
        sel = __reduce_min_sync(0xffffffffu, c2);
    }
}

// ---------------------------------------------------------------------------
// Kernel 2: 64 nearest neighbors per centroid, sorted ascending (tie: lower
// index). One block (128 thr) per centroid; d2 in smem; 64 rounds of block
// argmin via REDUX; cooperative warp rescan for the owner thread.
// ---------------------------------------------------------------------------
__global__ void __launch_bounds__(128) knn_kernel(const float* __restrict__ pos,
                                                  const float* __restrict__ pos_s)
{
    __shared__ float sd[Pp];           // 32 KB
    const int b = blockIdx.y, m = blockIdx.x, tid = threadIdx.x;
    const int bm = b * Mm + m;
    const float* pb = pos + (size_t)b * Pp * 3;
    const float cx = pos_s[bm * 3], cy = pos_s[bm * 3 + 1], cz = pos_s[bm * 3 + 2];

#pragma unroll 4
    for (int i = 0; i < 64; i++) {
        int p = tid + i * 128;
        float dx = __fsub_rn(cx, pb[3 * p]);
        float dy = __fsub_rn(cy, pb[3 * p + 1]);
        float dz = __fsub_rn(cz, pb[3 * p + 2]);
        sd[p] = __fadd_rn(__fadd_rn(__fmul_rn(dx, dx), __fmul_rn(dy, dy)),
                          __fmul_rn(dz, dz));
    }
    __syncthreads();

    unsigned lv = 0x7f800000u;   // +inf bits
    unsigned li = 0xffffffffu;
#pragma unroll 4
    for (int i = 0; i < 64; i++) {
        int p = tid + i * 128;
        unsigned v = __float_as_uint(sd[p]);   // d2 >= 0 -> bit order == numeric
        if (v < lv) { lv = v; li = (unsigned)p; }
    }

    __shared__ unsigned swv[4];
    __shared__ unsigned swi[4];
    __shared__ unsigned sgi;

    const unsigned wid = tid >> 5;

    for (int r = 0; r < NB; r++) {
        unsigned wv = __reduce_min_sync(0xffffffffu, lv);
        unsigned cand = (lv == wv) ? li : 0xffffffffu;
        unsigned wi = __reduce_min_sync(0xffffffffu, cand);
        if ((tid & 31) == 0) { swv[wid] = wv; swi[wid] = wi; }
        __syncthreads();
        if (tid == 0) {
            unsigned gv = swv[0], gi = swi[0];
#pragma unroll
            for (int w = 1; w < 4; w++)
                if (swv[w] < gv || (swv[w] == gv && swi[w] < gi)) { gv = swv[w]; gi = swi[w]; }
            sgi = gi;
            g_nn_idx[bm * NB + r] = (int)gi;
            g_nn_d2 [bm * NB + r] = __uint_as_float(gv);
        }
        __syncthreads();
        unsigned sel = sgi;
        unsigned ot = sel & 127u;          // owner thread within block
        if (wid == (ot >> 5)) {            // owner warp: cooperative rescan
            if (tid == (int)ot) sd[sel] = CUDART_INF_F;
            __syncwarp();
            int ln = tid & 31;
            unsigned v0 = __float_as_uint(sd[ot + (unsigned)(2 * ln) * 128u]);
            unsigned v1 = __float_as_uint(sd[ot + (unsigned)(2 * ln + 1) * 128u]);
            unsigned mv = min(v0, v1);
            unsigned mi = (v0 <= v1) ? (ot + (unsigned)(2 * ln) * 128u)
                                     : (ot + (unsigned)(2 * ln + 1) * 128u);
            unsigned rv = __reduce_min_sync(0xffffffffu, mv);
            unsigned rc = (mv == rv) ? mi : 0xffffffffu;
            unsigned ri = __reduce_min_sync(0xffffffffu, rc);
            if (tid == (int)ot) { lv = rv; li = ri; }
        }
    }
}

// ---------------------------------------------------------------------------
// Kernel 3: per-centroid MLP for both branches, packed f32x2 FMAs.
// Block 256 = (tx 32, ty 8). red buffer aliases h1T (saves 8KB smem).
// ---------------------------------------------------------------------------
#define HT_STRIDE 68

template<int K, int H1, int H2>
__device__ __forceinline__ void run_branch(
    const float* __restrict__ hT, float* __restrict__ h1T,
    const float* __restrict__ sd2,
    const float* __restrict__ W1, const float* __restrict__ B1b,
    const float* __restrict__ W2, const float* __restrict__ B2b,
    float* __restrict__ outrow, float r2, int tx, int ty, int tid)
{
    constexpr int KV = K / 8;     // neighbors per thread
    constexpr int IU = H1 / 32;   // hidden1 channels per thread
    constexpr int JU = H2 / 32;   // hidden2 channels per thread
    constexpr int IU2 = IU / 2, JU2 = JU / 2;

    // ---- GEMM1: h1[i][k] = relu(sum_c hT[c][k]*W1[c][i] + b1[i]) ----
    {
        u64 acc[KV][IU2];
#pragma unroll
        for (int v = 0; v < KV; v++)
#pragma unroll
            for (int u = 0; u < IU2; u++) acc[v][u] = 0ull;

        for (int c = 0; c < 67; c++) {
            float a[KV];
            const float4* hp = (const float4*)(hT + c * HT_STRIDE + ty * KV);
#pragma unroll
            for (int q = 0; q < KV / 4; q++) {
                float4 t4 = hp[q];
                a[4*q] = t4.x; a[4*q+1] = t4.y; a[4*q+2] = t4.z; a[4*q+3] = t4.w;
            }
            u64 aa[KV];
#pragma unroll
            for (int v = 0; v < KV; v++) aa[v] = pk2(a[v], a[v]);

            u64 bb[IU2];
            const float* wp = W1 + c * H1 + tx * IU;
            if constexpr (IU == 4) {
                float4 t4 = *(const float4*)wp;
                bb[0] = pk2(t4.x, t4.y); bb[1] = pk2(t4.z, t4.w);
            } else {
                float2 t2 = *(const float2*)wp;
                bb[0] = pk2(t2.x, t2.y);
            }
#pragma unroll
            for (int v = 0; v < KV; v++)
#pragma unroll
                for (int u = 0; u < IU2; u++)
                    acc[v][u] = fma2(aa[v], bb[u], acc[v][u]);
        }
        float bias[IU];
#pragma unroll
        for (int u = 0; u < IU; u++) bias[u] = B1b[tx * IU + u];
#pragma unroll
        for (int u = 0; u < IU2; u++) {
#pragma unroll
            for (int v = 0; v < KV; v++) {
                float lo, hi;
                upk2(lo, hi, acc[v][u]);
                int i0 = tx * IU + 2 * u;
                int k  = ty * KV + v;
                h1T[i0 * HT_STRIDE + k]       = fmaxf(lo + bias[2*u],     0.f);
                h1T[(i0 + 1) * HT_STRIDE + k] = fmaxf(hi + bias[2*u + 1], 0.f);
            }
        }
    }
    __syncthreads();

    // ---- GEMM2 + masked max over k ----
    {
        u64 acc[KV][JU2];
#pragma unroll
        for (int v = 0; v < KV; v++)
#pragma unroll
            for (int u = 0; u < JU2; u++) acc[v][u] = 0ull;

        for (int i = 0; i < H1; i++) {
            float a[KV];
            const float4* hp = (const float4*)(h1T + i * HT_STRIDE + ty * KV);
#pragma unroll
            for (int q = 0; q < KV / 4; q++) {
                float4 t4 = hp[q];
                a[4*q] = t4.x; a[4*q+1] = t4.y; a[4*q+2] = t4.z; a[4*q+3] = t4.w;
            }
            u64 aa[KV];
#pragma unroll
            for (int v = 0; v < KV; v++) aa[v] = pk2(a[v], a[v]);

            u64 bb[JU2];
            const float4* wp = (const float4*)(W2 + i * H2 + tx * JU);
#pragma unroll
            for (int q = 0; q < JU / 4; q++) {
                float4 t4 = wp[q];
                bb[2*q]   = pk2(t4.x, t4.y);
                bb[2*q+1] = pk2(t4.z, t4.w);
            }
#pragma unroll
            for (int v = 0; v < KV; v++)
#pragma unroll
                for (int u = 0; u < JU2; u++)
                    acc[v][u] = fma2(aa[v], bb[u], acc[v][u]);
        }

        float b2[JU];
#pragma unroll
        for (int u = 0; u < JU; u++) b2[u] = B2b[tx * JU + u];
        float mx[JU];
#pragma unroll
        for (int u = 0; u < JU; u++) mx[u] = -1e30f;
#pragma unroll
        for (int v = 0; v < KV; v++) {
            bool ok = (sd2[ty * KV + v] <= r2);
#pragma unroll
            for (int u = 0; u < JU2; u++) {
                float lo, hi;
                upk2(lo, hi, acc[v][u]);
                float v0 = fmaxf(lo + b2[2*u],     0.f);
                float v1 = fmaxf(hi + b2[2*u + 1], 0.f);
                if (!ok) { v0 = -1e30f; v1 = -1e30f; }
                mx[2*u]     = fmaxf(mx[2*u],     v0);
                mx[2*u + 1] = fmaxf(mx[2*u + 1], v1);
            }
        }

        // red aliases h1T: all h1T reads are done (acc complete), sync then reuse
        __syncthreads();
        float* red = h1T;   // 8 * H2 <= 2048 floats, fits in h1T region
#pragma unroll
        for (int u = 0; u < JU; u++) red[ty * H2 + tx * JU + u] = mx[u];
        __syncthreads();
        for (int j = tid; j < H2; j += 256) {
            float mm = red[j];
#pragma unroll
            for (int w = 1; w < 8; w++) mm = fmaxf(mm, red[w * H2 + j]);
            outrow[j] = mm;
        }
        __syncthreads();
    }
}

__global__ void __launch_bounds__(256, 2) mlp_kernel(
    const float* __restrict__ x, const float* __restrict__ pos,
    const float* __restrict__ pos_s,
    const float* __restrict__ w1_0, const float* __restrict__ b1_0,
    const float* __restrict__ w1_1, const float* __restrict__ b1_1,
    const float* __restrict__ w2_0, const float* __restrict__ b2_0,
    const float* __restrict__ w2_1, const float* __restrict__ b2_1,
    float* __restrict__ out)
{
    extern __shared__ float sm[];
    float* hT  = sm;                         // 67 * 68 = 4556 floats
    float* h1T = hT + 67 * HT_STRIDE;        // 128 * 68 = 8704 floats (also red)
    float* sd2 = h1T + 128 * HT_STRIDE;      // 64
    float* sps = sd2 + 64;                   // 4
    int*   snn = (int*)(sps + 4);            // 64

    const int b = blockIdx.y, m = blockIdx.x, tid = threadIdx.x;
    const int tx = tid & 31, ty = tid >> 5;
    const int bm = b * Mm + m;

    if (tid < NB) {
        snn[tid] = g_nn_idx[bm * NB + tid];
        sd2[tid] = g_nn_d2 [bm * NB + tid];
    }
    if (tid < 3) sps[tid] = pos_s[bm * 3 + tid];
    __syncthreads();

    // gather features (transposed): hT[c][k]
    for (int t = tid; t < NB * Cc; t += 256) {
        int k = t >> 6, c = t & 63;
        hT[c * HT_STRIDE + k] = x[((size_t)(b * Pp) + snn[k]) * Cc + c];
    }
    // relative positions: hT[64+d][k]
    for (int t = tid; t < NB * 3; t += 256) {
        int k = t / 3, d = t - 3 * k;
        hT[(64 + d) * HT_STRIDE + k] =
            __fsub_rn(pos[((size_t)(b * Pp) + snn[k]) * 3 + d], sps[d]);
    }
    __syncthreads();

    const float R2A = (float)(0.2 * 0.2);
    const float R2B = (float)(0.4 * 0.4);

    float* outrow = out + (size_t)bm * OUTC;
    // branch 2: K=64, 67->128->256, output channels [128,384)
    run_branch<64, 128, 256>(hT, h1T, sd2, w2_0, b2_0, w2_1, b2_1,
                             outrow + 128, R2B, tx, ty, tid);
    // branch 1: K=32 (prefix of sorted 64-NN), 67->64->128, channels [0,128)
    run_branch<32, 64, 128>(hT, h1T, sd2, w1_0, b1_0, w1_1, b1_1,
                            outrow, R2A, tx, ty, tid);
}

// ---------------------------------------------------------------------------
// launch
// ---------------------------------------------------------------------------
extern "C" void kernel_launch(void* const* d_in, const int* in_sizes, int n_in,
                              void* d_out, int out_size)
{
    const float* x    = (const float*)d_in[0];
    const float* pos  = (const float*)d_in[1];
    const float* w1_0 = (const float*)d_in[2];
    const float* b1_0 = (const float*)d_in[3];
    const float* w1_1 = (const float*)d_in[4];
    const float* b1_1 = (const float*)d_in[5];
    const float* w2_0 = (const float*)d_in[6];
    const float* b2_0 = (const float*)d_in[7];
    const float* w2_1 = (const float*)d_in[8];
    const float* b2_1 = (const float*)d_in[9];

    float* out   = (float*)d_out;
    float* pos_s = out + (size_t)Bb * Mm * OUTC;   // [out | pos_s] layout

    const int mlp_smem = (67 * HT_STRIDE + 128 * HT_STRIDE + 64 + 4 + 64) * 4;
    cudaFuncSetAttribute(mlp_kernel, cudaFuncAttributeMaxDynamicSharedMemorySize, mlp_smem);

    fps_kernel<<<Bb, 1024>>>(pos, pos_s);

    dim3 g(Mm, Bb);
    knn_kernel<<<g, 128>>>(pos, pos_s);

    mlp_kernel<<<g, 256, mlp_smem>>>(x, pos, pos_s,
                                     w1_0, b1_0, w1_1, b1_1,
                                     w2_0, b2_0, w2_1, b2_1, out);
}

// round 7
// speedup vs baseline: 1.0004x; 1.0004x over previous
#include <cuda_runtime.h>
#include <math_constants.h>

#define Bb 4
#define Pp 8192
#define Cc 64
#define Mm 2048
#define NB 64
#define OUTC 384

// scratch (allocation-free rule: __device__ globals)
__device__ int   g_nn_idx[Bb*Mm*NB];
__device__ float g_nn_d2 [Bb*Mm*NB];

// ---------------- packed f32x2 helpers (bitwise == two scalar rn ops) -------
typedef unsigned long long u64;

__device__ __forceinline__ u64 pk2(float lo, float hi) {
    u64 r; asm("mov.b64 %0, {%1, %2};" : "=l"(r) : "f"(lo), "f"(hi)); return r;
}
__device__ __forceinline__ void upk2(float& lo, float& hi, u64 v) {
    asm("mov.b64 {%0, %1}, %2;" : "=f"(lo), "=f"(hi) : "l"(v));
}
__device__ __forceinline__ u64 add2(u64 a, u64 b) {
    u64 d; asm("add.rn.f32x2 %0, %1, %2;" : "=l"(d) : "l"(a), "l"(b)); return d;
}
__device__ __forceinline__ u64 mul2(u64 a, u64 b) {
    u64 d; asm("mul.rn.f32x2 %0, %1, %2;" : "=l"(d) : "l"(a), "l"(b)); return d;
}
__device__ __forceinline__ u64 fma2(u64 a, u64 b, u64 c) {
    u64 d; asm("fma.rn.f32x2 %0, %1, %2, %3;" : "=l"(d) : "l"(a), "l"(b), "l"(c)); return d;
}

// ---------------------------------------------------------------------------
// Kernel 1: farthest point sampling, one block per batch.
// Bitwise-identical selection to the JAX scan: ((dx*dx+dy*dy)+dz*dz) rn ops,
// no fma contraction; argmax ties -> lowest index.
// Single barrier per iteration: warp REDUX -> leaders write double-buffered
// smem -> bar -> every warp re-reduces the 32 leader values itself.
// ---------------------------------------------------------------------------
__global__ void __launch_bounds__(1024) fps_kernel(const float* __restrict__ pos,
                                                   float* __restrict__ pos_s)
{
    const int b = blockIdx.x;
    const float* pb = pos + (size_t)b * Pp * 3;
    float* ps = pos_s + (size_t)b * Mm * 3;
    const int tid = threadIdx.x;
    const int lane = tid & 31, wrp = tid >> 5;

    u64 px2[4], py2[4], pz2[4];
    unsigned mind[8];
#pragma unroll
    for (int q = 0; q < 4; q++) {
        int p0 = tid + (2 * q) * 1024;
        int p1 = tid + (2 * q + 1) * 1024;
        px2[q] = pk2(pb[3 * p0],     pb[3 * p1]);
        py2[q] = pk2(pb[3 * p0 + 1], pb[3 * p1 + 1]);
        pz2[q] = pk2(pb[3 * p0 + 2], pb[3 * p1 + 2]);
    }
#pragma unroll
    for (int i = 0; i < 8; i++) mind[i] = __float_as_uint(1e30f);

    __shared__ unsigned swv[2][32];
    __shared__ unsigned swi[2][32];

    unsigned sel = 0;
    for (int t = 0; t < Mm; t++) {
        float lx = pb[3 * sel], ly = pb[3 * sel + 1], lz = pb[3 * sel + 2];
        if (tid == 0) { ps[3 * t] = lx; ps[3 * t + 1] = ly; ps[3 * t + 2] = lz; }

        u64 nx2 = pk2(-lx, -lx);
        u64 ny2 = pk2(-ly, -ly);
        u64 nz2 = pk2(-lz, -lz);

#pragma unroll
        for (int q = 0; q < 4; q++) {
            u64 dx = add2(px2[q], nx2);
            u64 dy = add2(py2[q], ny2);
            u64 dz = add2(pz2[q], nz2);
            u64 s  = add2(add2(mul2(dx, dx), mul2(dy, dy)), mul2(dz, dz));
            float dlo, dhi;
            upk2(dlo, dhi, s);
            mind[2 * q]     = min(mind[2 * q],     __float_as_uint(dlo));
            mind[2 * q + 1] = min(mind[2 * q + 1], __float_as_uint(dhi));
        }
        // 7-op max tree (d2 >= 0 -> uint order == float order)
        unsigned m01 = max(mind[0], mind[1]), m23 = max(mind[2], mind[3]);
        unsigned m45 = max(mind[4], mind[5]), m67 = max(mind[6], mind[7]);
        unsigned bv  = max(max(m01, m23), max(m45, m67));

        // warp argmax (value first, then lowest point index among matches)
        unsigned wv = __reduce_max_sync(0xffffffffu, bv);
        unsigned cand = 0xffffffffu;
        if (bv == wv) {
#pragma unroll
            for (int i = 7; i >= 0; i--)
                if (mind[i] == wv) cand = (unsigned)(tid + (i << 10));
        }
        unsigned wi = __reduce_min_sync(0xffffffffu, cand);

        const int buf = t & 1;
        if (lane == 0) { swv[buf][wrp] = wv; swi[buf][wrp] = wi; }
        __syncthreads();

        // every warp resolves the block winner itself (no 2nd barrier)
        unsigned v  = swv[buf][lane];
        unsigned ii = swi[buf][lane];
        unsigned gv = __reduce_max_sync(0xffffffffu, v);
        unsigned c2 = (v == gv) ? ii : 0xffffffffu;
        sel = __reduce_min_sync(0xffffffffu, c2);
    }
}

// ---------------------------------------------------------------------------
// Kernel 2: 64 nearest neighbors per centroid, sorted ascending (tie: lower
// index). One block (128 thr) per centroid; d2 in smem; 64 rounds of block
// argmin via REDUX; cooperative warp rescan for the owner thread.
// ---------------------------------------------------------------------------
__global__ void __launch_bounds__(128) knn_kernel(const float* __restrict__ pos,
                                                  const float* __restrict__ pos_s)
{
    __shared__ float sd[Pp];           // 32 KB
    const int b = blockIdx.y, m = blockIdx.x, tid = threadIdx.x;
    const int bm = b * Mm + m;
    const float* pb = pos + (size_t)b * Pp * 3;
    const float cx = pos_s[bm * 3], cy = pos_s[bm * 3 + 1], cz = pos_s[bm * 3 + 2];

#pragma unroll 4
    for (int i = 0; i < 64; i++) {
        int p = tid + i * 128;
        float dx = __fsub_rn(cx, pb[3 * p]);
        float dy = __fsub_rn(cy, pb[3 * p + 1]);
        float dz = __fsub_rn(cz, pb[3 * p + 2]);
        sd[p] = __fadd_rn(__fadd_rn(__fmul_rn(dx, dx), __fmul_rn(dy, dy)),
                          __fmul_rn(dz, dz));
    }
    __syncthreads();

    unsigned lv = 0x7f800000u;   // +inf bits
    unsigned li = 0xffffffffu;
#pragma unroll 4
    for (int i = 0; i < 64; i++) {
        int p = tid + i * 128;
        unsigned v = __float_as_uint(sd[p]);   // d2 >= 0 -> bit order == numeric
        if (v < lv) { lv = v; li = (unsigned)p; }
    }

    __shared__ unsigned swv[4];
    __shared__ unsigned swi[4];
    __shared__ unsigned sgi;

    const unsigned wid = tid >> 5;

    for (int r = 0; r < NB; r++) {
        unsigned wv = __reduce_min_sync(0xffffffffu, lv);
        unsigned cand = (lv == wv) ? li : 0xffffffffu;
        unsigned wi = __reduce_min_sync(0xffffffffu, cand);
        if ((tid & 31) == 0) { swv[wid] = wv; swi[wid] = wi; }
        __syncthreads();
        if (tid == 0) {
            unsigned gv = swv[0], gi = swi[0];
#pragma unroll
            for (int w = 1; w < 4; w++)
                if (swv[w] < gv || (swv[w] == gv && swi[w] < gi)) { gv = swv[w]; gi = swi[w]; }
            sgi = gi;
            g_nn_idx[bm * NB + r] = (int)gi;
            g_nn_d2 [bm * NB + r] = __uint_as_float(gv);
        }
        __syncthreads();
        unsigned sel = sgi;
        unsigned ot = sel & 127u;          // owner thread within block
        if (wid == (ot >> 5)) {            // owner warp: cooperative rescan
            if (tid == (int)ot) sd[sel] = CUDART_INF_F;
            __syncwarp();
            int ln = tid & 31;
            unsigned v0 = __float_as_uint(sd[ot + (unsigned)(2 * ln) * 128u]);
            unsigned v1 = __float_as_uint(sd[ot + (unsigned)(2 * ln + 1) * 128u]);
            unsigned mv = min(v0, v1);
            unsigned mi = (v0 <= v1) ? (ot + (unsigned)(2 * ln) * 128u)
                                     : (ot + (unsigned)(2 * ln + 1) * 128u);
            unsigned rv = __reduce_min_sync(0xffffffffu, mv);
            unsigned rc = (mv == rv) ? mi : 0xffffffffu;
            unsigned ri = __reduce_min_sync(0xffffffffu, rc);
            if (tid == (int)ot) { lv = rv; li = ri; }
        }
    }
}

// ---------------------------------------------------------------------------
// Kernel 3: per-centroid MLP for both branches, packed f32x2 FMAs.
// Block 256 = (tx 32, ty 8). red buffer aliases h1T (saves 8KB smem).
// ---------------------------------------------------------------------------
#define HT_STRIDE 68

template<int K, int H1, int H2>
__device__ __forceinline__ void run_branch(
    const float* __restrict__ hT, float* __restrict__ h1T,
    const float* __restrict__ sd2,
    const float* __restrict__ W1, const float* __restrict__ B1b,
    const float* __restrict__ W2, const float* __restrict__ B2b,
    float* __restrict__ outrow, float r2, int tx, int ty, int tid)
{
    constexpr int KV = K / 8;     // neighbors per thread
    constexpr int IU = H1 / 32;   // hidden1 channels per thread
    constexpr int JU = H2 / 32;   // hidden2 channels per thread
    constexpr int IU2 = IU / 2, JU2 = JU / 2;

    // ---- GEMM1: h1[i][k] = relu(sum_c hT[c][k]*W1[c][i] + b1[i]) ----
    {
        u64 acc[KV][IU2];
#pragma unroll
        for (int v = 0; v < KV; v++)
#pragma unroll
            for (int u = 0; u < IU2; u++) acc[v][u] = 0ull;

        for (int c = 0; c < 67; c++) {
            float a[KV];
            const float4* hp = (const float4*)(hT + c * HT_STRIDE + ty * KV);
#pragma unroll
            for (int q = 0; q < KV / 4; q++) {
                float4 t4 = hp[q];
                a[4*q] = t4.x; a[4*q+1] = t4.y; a[4*q+2] = t4.z; a[4*q+3] = t4.w;
            }
            u64 aa[KV];
#pragma unroll
            for (int v = 0; v < KV; v++) aa[v] = pk2(a[v], a[v]);

            u64 bb[IU2];
            const float* wp = W1 + c * H1 + tx * IU;
            if constexpr (IU == 4) {
                float4 t4 = *(const float4*)wp;
                bb[0] = pk2(t4.x, t4.y); bb[1] = pk2(t4.z, t4.w);
            } else {
                float2 t2 = *(const float2*)wp;
                bb[0] = pk2(t2.x, t2.y);
            }
#pragma unroll
            for (int v = 0; v < KV; v++)
#pragma unroll
                for (int u = 0; u < IU2; u++)
                    acc[v][u] = fma2(aa[v], bb[u], acc[v][u]);
        }
        float bias[IU];
#pragma unroll
        for (int u = 0; u < IU; u++) bias[u] = B1b[tx * IU + u];
#pragma unroll
        for (int u = 0; u < IU2; u++) {
#pragma unroll
            for (int v = 0; v < KV; v++) {
                float lo, hi;
                upk2(lo, hi, acc[v][u]);
                int i0 = tx * IU + 2 * u;
                int k  = ty * KV + v;
                h1T[i0 * HT_STRIDE + k]       = fmaxf(lo + bias[2*u],     0.f);
                h1T[(i0 + 1) * HT_STRIDE + k] = fmaxf(hi + bias[2*u + 1], 0.f);
            }
        }
    }
    __syncthreads();

    // ---- GEMM2 + masked max over k ----
    {
        u64 acc[KV][JU2];
#pragma unroll
        for (int v = 0; v < KV; v++)
#pragma unroll
            for (int u = 0; u < JU2; u++) acc[v][u] = 0ull;

        for (int i = 0; i < H1; i++) {
            float a[KV];
            const float4* hp = (const float4*)(h1T + i * HT_STRIDE + ty * KV);
#pragma unroll
            for (int q = 0; q < KV / 4; q++) {
                float4 t4 = hp[q];
                a[4*q] = t4.x; a[4*q+1] = t4.y; a[4*q+2] = t4.z; a[4*q+3] = t4.w;
            }
            u64 aa[KV];
#pragma unroll
            for (int v = 0; v < KV; v++) aa[v] = pk2(a[v], a[v]);

            u64 bb[JU2];
            const float4* wp = (const float4*)(W2 + i * H2 + tx * JU);
#pragma unroll
            for (int q = 0; q < JU / 4; q++) {
                float4 t4 = wp[q];
                bb[2*q]   = pk2(t4.x, t4.y);
                bb[2*q+1] = pk2(t4.z, t4.w);
            }
#pragma unroll
            for (int v = 0; v < KV; v++)
#pragma unroll
                for (int u = 0; u < JU2; u++)
                    acc[v][u] = fma2(aa[v], bb[u], acc[v][u]);
        }

        float b2[JU];
#pragma unroll
        for (int u = 0; u < JU; u++) b2[u] = B2b[tx * JU + u];
        float mx[JU];
#pragma unroll
        for (int u = 0; u < JU; u++) mx[u] = -1e30f;
#pragma unroll
        for (int v = 0; v < KV; v++) {
            bool ok = (sd2[ty * KV + v] <= r2);
#pragma unroll
            for (int u = 0; u < JU2; u++) {
                float lo, hi;
                upk2(lo, hi, acc[v][u]);
                float v0 = fmaxf(lo + b2[2*u],     0.f);
                float v1 = fmaxf(hi + b2[2*u + 1], 0.f);
                if (!ok) { v0 = -1e30f; v1 = -1e30f; }
                mx[2*u]     = fmaxf(mx[2*u],     v0);
                mx[2*u + 1] = fmaxf(mx[2*u + 1], v1);
            }
        }

        // red aliases h1T: all h1T reads are done (acc complete), sync then reuse
        __syncthreads();
        float* red = h1T;   // 8 * H2 <= 2048 floats, fits in h1T region
#pragma unroll
        for (int u = 0; u < JU; u++) red[ty * H2 + tx * JU + u] = mx[u];
        __syncthreads();
        for (int j = tid; j < H2; j += 256) {
            float mm = red[j];
#pragma unroll
            for (int w = 1; w < 8; w++) mm = fmaxf(mm, red[w * H2 + j]);
            outrow[j] = mm;
        }
        __syncthreads();
    }
}

__global__ void __launch_bounds__(256, 2) mlp_kernel(
    const float* __restrict__ x, const float* __restrict__ pos,
    const float* __restrict__ pos_s,
    const float* __restrict__ w1_0, const float* __restrict__ b1_0,
    const float* __restrict__ w1_1, const float* __restrict__ b1_1,
    const float* __restrict__ w2_0, const float* __restrict__ b2_0,
    const float* __restrict__ w2_1, const float* __restrict__ b2_1,
    float* __restrict__ out)
{
    extern __shared__ float sm[];
    float* hT  = sm;                         // 67 * 68 = 4556 floats
    float* h1T = hT + 67 * HT_STRIDE;        // 128 * 68 = 8704 floats (also red)
    float* sd2 = h1T + 128 * HT_STRIDE;      // 64
    float* sps = sd2 + 64;                   // 4
    int*   snn = (int*)(sps + 4);            // 64

    const int b = blockIdx.y, m = blockIdx.x, tid = threadIdx.x;
    const int tx = tid & 31, ty = tid >> 5;
    const int bm = b * Mm + m;

    if (tid < NB) {
        snn[tid] = g_nn_idx[bm * NB + tid];
        sd2[tid] = g_nn_d2 [bm * NB + tid];
    }
    if (tid < 3) sps[tid] = pos_s[bm * 3 + tid];
    __syncthreads();

    // gather features (transposed): hT[c][k]
    for (int t = tid; t < NB * Cc; t += 256) {
        int k = t >> 6, c = t & 63;
        hT[c * HT_STRIDE + k] = x[((size_t)(b * Pp) + snn[k]) * Cc + c];
    }
    // relative positions: hT[64+d][k]
    for (int t = tid; t < NB * 3; t += 256) {
        int k = t / 3, d = t - 3 * k;
        hT[(64 + d) * HT_STRIDE + k] =
            __fsub_rn(pos[((size_t)(b * Pp) + snn[k]) * 3 + d], sps[d]);
    }
    __syncthreads();

    const float R2A = (float)(0.2 * 0.2);
    const float R2B = (float)(0.4 * 0.4);

    float* outrow = out + (size_t)bm * OUTC;
    // branch 2: K=64, 67->128->256, output channels [128,384)
    run_branch<64, 128, 256>(hT, h1T, sd2, w2_0, b2_0, w2_1, b2_1,
                             outrow + 128, R2B, tx, ty, tid);
    // branch 1: K=32 (prefix of sorted 64-NN), 67->64->128, channels [0,128)
    run_branch<32, 64, 128>(hT, h1T, sd2, w1_0, b1_0, w1_1, b1_1,
                            outrow, R2A, tx, ty, tid);
}

// ---------------------------------------------------------------------------
// launch
// ---------------------------------------------------------------------------
extern "C" void kernel_launch(void* const* d_in, const int* in_sizes, int n_in,
                              void* d_out, int out_size)
{
    const float* x    = (const float*)d_in[0];
    const float* pos  = (const float*)d_in[1];
    const float* w1_0 = (const float*)d_in[2];
    const float* b1_0 = (const float*)d_in[3];
    const float* w1_1 = (const float*)d_in[4];
    const float* b1_1 = (const float*)d_in[5];
    const float* w2_0 = (const float*)d_in[6];
    const float* b2_0 = (const float*)d_in[7];
    const float* w2_1 = (const float*)d_in[8];
    const float* b2_1 = (const float*)d_in[9];

    float* out   = (float*)d_out;
    float* pos_s = out + (size_t)Bb * Mm * OUTC;   // [out | pos_s] layout

    const int mlp_smem = (67 * HT_STRIDE + 128 * HT_STRIDE + 64 + 4 + 64) * 4;
    cudaFuncSetAttribute(mlp_kernel, cudaFuncAttributeMaxDynamicSharedMemorySize, mlp_smem);

    fps_kernel<<<Bb, 1024>>>(pos, pos_s);

    dim3 g(Mm, Bb);
    knn_kernel<<<g, 128>>>(pos, pos_s);

    mlp_kernel<<<g, 256, mlp_smem>>>(x, pos, pos_s,
                                     w1_0, b1_0, w1_1, b1_1,
                                     w2_0, b2_0, w2_1, b2_1, out);
}

// round 8
// speedup vs baseline: 1.0360x; 1.0356x over previous
#include <cuda_runtime.h>
#include <math_constants.h>

#define Bb 4
#define Pp 8192
#define Cc 64
#define Mm 2048
#define NB 64
#define OUTC 384

// scratch (allocation-free rule: __device__ globals)
__device__ int   g_nn_idx[Bb*Mm*NB];
__device__ float g_nn_d2 [Bb*Mm*NB];

// ---------------- packed f32x2 helpers (bitwise == two scalar rn ops) -------
typedef unsigned long long u64;

__device__ __forceinline__ u64 pk2(float lo, float hi) {
    u64 r; asm("mov.b64 %0, {%1, %2};" : "=l"(r) : "f"(lo), "f"(hi)); return r;
}
__device__ __forceinline__ void upk2(float& lo, float& hi, u64 v) {
    asm("mov.b64 {%0, %1}, %2;" : "=f"(lo), "=f"(hi) : "l"(v));
}
__device__ __forceinline__ u64 add2(u64 a, u64 b) {
    u64 d; asm("add.rn.f32x2 %0, %1, %2;" : "=l"(d) : "l"(a), "l"(b)); return d;
}
__device__ __forceinline__ u64 mul2(u64 a, u64 b) {
    u64 d; asm("mul.rn.f32x2 %0, %1, %2;" : "=l"(d) : "l"(a), "l"(b)); return d;
}
__device__ __forceinline__ u64 fma2(u64 a, u64 b, u64 c) {
    u64 d; asm("fma.rn.f32x2 %0, %1, %2, %3;" : "=l"(d) : "l"(a), "l"(b), "l"(c)); return d;
}

// ---------------------------------------------------------------------------
// Kernel 1: farthest point sampling, one block per batch.
// Bitwise-identical selection to the JAX scan: ((dx*dx+dy*dy)+dz*dz) rn ops,
// no fma contraction; argmax ties -> lowest index.
// ---------------------------------------------------------------------------
__global__ void __launch_bounds__(1024) fps_kernel(const float* __restrict__ pos,
                                                   float* __restrict__ pos_s)
{
    const int b = blockIdx.x;
    const float* pb = pos + (size_t)b * Pp * 3;
    float* ps = pos_s + (size_t)b * Mm * 3;
    const int tid = threadIdx.x;
    const int lane = tid & 31, wrp = tid >> 5;

    u64 px2[4], py2[4], pz2[4];
    unsigned mind[8];
#pragma unroll
    for (int q = 0; q < 4; q++) {
        int p0 = tid + (2 * q) * 1024;
        int p1 = tid + (2 * q + 1) * 1024;
        px2[q] = pk2(pb[3 * p0],     pb[3 * p1]);
        py2[q] = pk2(pb[3 * p0 + 1], pb[3 * p1 + 1]);
        pz2[q] = pk2(pb[3 * p0 + 2], pb[3 * p1 + 2]);
    }
#pragma unroll
    for (int i = 0; i < 8; i++) mind[i] = __float_as_uint(1e30f);

    __shared__ unsigned swv[2][32];
    __shared__ unsigned swi[2][32];

    unsigned sel = 0;
    for (int t = 0; t < Mm; t++) {
        float lx = pb[3 * sel], ly = pb[3 * sel + 1], lz = pb[3 * sel + 2];
        if (tid == 0) { ps[3 * t] = lx; ps[3 * t + 1] = ly; ps[3 * t + 2] = lz; }

        u64 nx2 = pk2(-lx, -lx);
        u64 ny2 = pk2(-ly, -ly);
        u64 nz2 = pk2(-lz, -lz);

#pragma unroll
        for (int q = 0; q < 4; q++) {
            u64 dx = add2(px2[q], nx2);
            u64 dy = add2(py2[q], ny2);
            u64 dz = add2(pz2[q], nz2);
            u64 s  = add2(add2(mul2(dx, dx), mul2(dy, dy)), mul2(dz, dz));
            float dlo, dhi;
            upk2(dlo, dhi, s);
            mind[2 * q]     = min(mind[2 * q],     __float_as_uint(dlo));
            mind[2 * q + 1] = min(mind[2 * q + 1], __float_as_uint(dhi));
        }
        // 7-op max tree (d2 >= 0 -> uint order == float order)
        unsigned m01 = max(mind[0], mind[1]), m23 = max(mind[2], mind[3]);
        unsigned m45 = max(mind[4], mind[5]), m67 = max(mind[6], mind[7]);
        unsigned bv  = max(max(m01, m23), max(m45, m67));

        // warp argmax (value first, then lowest point index among matches)
        unsigned wv = __reduce_max_sync(0xffffffffu, bv);
        unsigned cand = 0xffffffffu;
        if (bv == wv) {
#pragma unroll
            for (int i = 7; i >= 0; i--)
                if (mind[i] == wv) cand = (unsigned)(tid + (i << 10));
        }
        unsigned wi = __reduce_min_sync(0xffffffffu, cand);

        const int buf = t & 1;
        if (lane == 0) { swv[buf][wrp] = wv; swi[buf][wrp] = wi; }
        __syncthreads();

        // every warp resolves the block winner itself (no 2nd barrier)
        unsigned v  = swv[buf][lane];
        unsigned ii = swi[buf][lane];
        unsigned gv = __reduce_max_sync(0xffffffffu, v);
        unsigned c2 = (v == gv) ? ii : 0xffffffffu;
        sel = __reduce_min_sync(0xffffffffu, c2);
    }
}

// ---------------------------------------------------------------------------
// Kernel 2: 64 nearest neighbors per centroid, sorted ascending (tie: lower
// index). One block (128 thr) per centroid.
// ---------------------------------------------------------------------------
__global__ void __launch_bounds__(128) knn_kernel(const float* __restrict__ pos,
                                                  const float* __restrict__ pos_s)
{
    __shared__ float sd[Pp];           // 32 KB
    const int b = blockIdx.y, m = blockIdx.x, tid = threadIdx.x;
    const int bm = b * Mm + m;
    const float* pb = pos + (size_t)b * Pp * 3;
    const float cx = pos_s[bm * 3], cy = pos_s[bm * 3 + 1], cz = pos_s[bm * 3 + 2];

#pragma unroll 4
    for (int i = 0; i < 64; i++) {
        int p = tid + i * 128;
        float dx = __fsub_rn(cx, pb[3 * p]);
        float dy = __fsub_rn(cy, pb[3 * p + 1]);
        float dz = __fsub_rn(cz, pb[3 * p + 2]);
        sd[p] = __fadd_rn(__fadd_rn(__fmul_rn(dx, dx), __fmul_rn(dy, dy)),
                          __fmul_rn(dz, dz));
    }
    __syncthreads();

    unsigned lv = 0x7f800000u;   // +inf bits
    unsigned li = 0xffffffffu;
#pragma unroll 4
    for (int i = 0; i < 64; i++) {
        int p = tid + i * 128;
        unsigned v = __float_as_uint(sd[p]);   // d2 >= 0 -> bit order == numeric
        if (v < lv) { lv = v; li = (unsigned)p; }
    }

    __shared__ unsigned swv[4];
    __shared__ unsigned swi[4];
    __shared__ unsigned sgi;

    const unsigned wid = tid >> 5;

    for (int r = 0; r < NB; r++) {
        unsigned wv = __reduce_min_sync(0xffffffffu, lv);
        unsigned cand = (lv == wv) ? li : 0xffffffffu;
        unsigned wi = __reduce_min_sync(0xffffffffu, cand);
        if ((tid & 31) == 0) { swv[wid] = wv; swi[wid] = wi; }
        __syncthreads();
        if (tid == 0) {
            unsigned gv = swv[0], gi = swi[0];
#pragma unroll
            for (int w = 1; w < 4; w++)
                if (swv[w] < gv || (swv[w] == gv && swi[w] < gi)) { gv = swv[w]; gi = swi[w]; }
            sgi = gi;
            g_nn_idx[bm * NB + r] = (int)gi;
            g_nn_d2 [bm * NB + r] = __uint_as_float(gv);
        }
        __syncthreads();
        unsigned sel = sgi;
        unsigned ot = sel & 127u;          // owner thread within block
        if (wid == (ot >> 5)) {            // owner warp: cooperative rescan
            if (tid == (int)ot) sd[sel] = CUDART_INF_F;
            __syncwarp();
            int ln = tid & 31;
            unsigned v0 = __float_as_uint(sd[ot + (unsigned)(2 * ln) * 128u]);
            unsigned v1 = __float_as_uint(sd[ot + (unsigned)(2 * ln + 1) * 128u]);
            unsigned mv = min(v0, v1);
            unsigned mi = (v0 <= v1) ? (ot + (unsigned)(2 * ln) * 128u)
                                     : (ot + (unsigned)(2 * ln + 1) * 128u);
            unsigned rv = __reduce_min_sync(0xffffffffu, mv);
            unsigned rc = (mv == rv) ? mi : 0xffffffffu;
            unsigned ri = __reduce_min_sync(0xffffffffu, rc);
            if (tid == (int)ot) { lv = rv; li = ri; }
        }
    }
}

// ---------------------------------------------------------------------------
// Kernel 3: per-centroid MLP for both branches, packed f32x2 FMAs.
// Block 256 = (tx 32, ty 8). red buffer aliases h1T.
// GEMM2 weight loads use 16B/lane strides (split channel halves) so each
// warp LDG.128 touches 4 L1 lines, not 8.
// ---------------------------------------------------------------------------
#define HT_STRIDE 68

template<int K, int H1, int H2>
__device__ __forceinline__ void run_branch(
    const float* __restrict__ hT, float* __restrict__ h1T,
    const float* __restrict__ sd2,
    const float* __restrict__ W1, const float* __restrict__ B1b,
    const float* __restrict__ W2, const float* __restrict__ B2b,
    float* __restrict__ outrow, float r2, int tx, int ty, int tid)
{
    constexpr int KV = K / 8;     // neighbors per thread
    constexpr int IU = H1 / 32;   // hidden1 channels per thread
    constexpr int JU = H2 / 32;   // hidden2 channels per thread
    constexpr int IU2 = IU / 2, JU2 = JU / 2;
    constexpr bool SPLIT = (JU == 8);   // split channel halves for 16B/lane LDG

    // ---- GEMM1: h1[i][k] = relu(sum_c hT[c][k]*W1[c][i] + b1[i]) ----
    {
        u64 acc[KV][IU2];
#pragma unroll
        for (int v = 0; v < KV; v++)
#pragma unroll
            for (int u = 0; u < IU2; u++) acc[v][u] = 0ull;

        for (int c = 0; c < 67; c++) {
            float a[KV];
            const float4* hp = (const float4*)(hT + c * HT_STRIDE + ty * KV);
#pragma unroll
            for (int q = 0; q < KV / 4; q++) {
                float4 t4 = hp[q];
                a[4*q] = t4.x; a[4*q+1] = t4.y; a[4*q+2] = t4.z; a[4*q+3] = t4.w;
            }
            u64 aa[KV];
#pragma unroll
            for (int v = 0; v < KV; v++) aa[v] = pk2(a[v], a[v]);

            u64 bb[IU2];
            const float* wp = W1 + c * H1 + tx * IU;
            if constexpr (IU == 4) {
                float4 t4 = *(const float4*)wp;
                bb[0] = pk2(t4.x, t4.y); bb[1] = pk2(t4.z, t4.w);
            } else {
                float2 t2 = *(const float2*)wp;
                bb[0] = pk2(t2.x, t2.y);
            }
#pragma unroll
            for (int v = 0; v < KV; v++)
#pragma unroll
                for (int u = 0; u < IU2; u++)
                    acc[v][u] = fma2(aa[v], bb[u], acc[v][u]);
        }
        float bias[IU];
#pragma unroll
        for (int u = 0; u < IU; u++) bias[u] = B1b[tx * IU + u];
#pragma unroll
        for (int u = 0; u < IU2; u++) {
#pragma unroll
            for (int v = 0; v < KV; v++) {
                float lo, hi;
                upk2(lo, hi, acc[v][u]);
                int i0 = tx * IU + 2 * u;
                int k  = ty * KV + v;
                h1T[i0 * HT_STRIDE + k]       = fmaxf(lo + bias[2*u],     0.f);
                h1T[(i0 + 1) * HT_STRIDE + k] = fmaxf(hi + bias[2*u + 1], 0.f);
            }
        }
    }
    __syncthreads();

    // ---- GEMM2 + masked max over k ----
    // Channel mapping per thread:
    //   SPLIT (JU=8):  u<4 -> tx*4+u ; u>=4 -> H2/2 + tx*4 + (u-4)
    //   else  (JU=4):  u   -> tx*4+u
    {
        u64 acc[KV][JU2];
#pragma unroll
        for (int v = 0; v < KV; v++)
#pragma unroll
            for (int u = 0; u < JU2; u++) acc[v][u] = 0ull;

        for (int i = 0; i < H1; i++) {
            float a[KV];
            const float4* hp = (const float4*)(h1T + i * HT_STRIDE + ty * KV);
#pragma unroll
            for (int q = 0; q < KV / 4; q++) {
                float4 t4 = hp[q];
                a[4*q] = t4.x; a[4*q+1] = t4.y; a[4*q+2] = t4.z; a[4*q+3] = t4.w;
            }
            u64 aa[KV];
#pragma unroll
            for (int v = 0; v < KV; v++) aa[v] = pk2(a[v], a[v]);

            u64 bb[JU2];
            if constexpr (SPLIT) {
                float4 tA = *(const float4*)(W2 + i * H2 + tx * 4);
                float4 tB = *(const float4*)(W2 + i * H2 + H2 / 2 + tx * 4);
                bb[0] = pk2(tA.x, tA.y); bb[1] = pk2(tA.z, tA.w);
                bb[2] = pk2(tB.x, tB.y); bb[3] = pk2(tB.z, tB.w);
            } else {
                float4 t4 = *(const float4*)(W2 + i * H2 + tx * 4);
                bb[0] = pk2(t4.x, t4.y); bb[1] = pk2(t4.z, t4.w);
            }
#pragma unroll
            for (int v = 0; v < KV; v++)
#pragma unroll
                for (int u = 0; u < JU2; u++)
                    acc[v][u] = fma2(aa[v], bb[u], acc[v][u]);
        }

        // channel index for mx[u]
        auto CH = [&](int u) -> int {
            if constexpr (SPLIT) return (u < 4) ? (tx * 4 + u) : (H2 / 2 + tx * 4 + (u - 4));
            else                 return tx * 4 + u;
        };

        float b2[JU];
#pragma unroll
        for (int u = 0; u < JU; u++) b2[u] = B2b[CH(u)];
        float mx[JU];
#pragma unroll
        for (int u = 0; u < JU; u++) mx[u] = -1e30f;
#pragma unroll
        for (int v = 0; v < KV; v++) {
            bool ok = (sd2[ty * KV + v] <= r2);
#pragma unroll
            for (int u = 0; u < JU2; u++) {
                float lo, hi;
                upk2(lo, hi, acc[v][u]);
                float v0 = fmaxf(lo + b2[2*u],     0.f);
                float v1 = fmaxf(hi + b2[2*u + 1], 0.f);
                if (!ok) { v0 = -1e30f; v1 = -1e30f; }
                mx[2*u]     = fmaxf(mx[2*u],     v0);
                mx[2*u + 1] = fmaxf(mx[2*u + 1], v1);
            }
        }

        // red aliases h1T: all h1T reads are done (acc complete), sync then reuse
        __syncthreads();
        float* red = h1T;   // 8 * H2 <= 2048 floats, fits in h1T region
#pragma unroll
        for (int u = 0; u < JU; u++) red[ty * H2 + CH(u)] = mx[u];
        __syncthreads();
        for (int j = tid; j < H2; j += 256) {
            float mm = red[j];
#pragma unroll
            for (int w = 1; w < 8; w++) mm = fmaxf(mm, red[w * H2 + j]);
            outrow[j] = mm;
        }
        __syncthreads();
    }
}

__global__ void __launch_bounds__(256, 2) mlp_kernel(
    const float* __restrict__ x, const float* __restrict__ pos,
    const float* __restrict__ pos_s,
    const float* __restrict__ w1_0, const float* __restrict__ b1_0,
    const float* __restrict__ w1_1, const float* __restrict__ b1_1,
    const float* __restrict__ w2_0, const float* __restrict__ b2_0,
    const float* __restrict__ w2_1, const float* __restrict__ b2_1,
    float* __restrict__ out)
{
    extern __shared__ float sm[];
    float* hT  = sm;                         // 67 * 68 = 4556 floats
    float* h1T = hT + 67 * HT_STRIDE;        // 128 * 68 = 8704 floats (also red)
    float* sd2 = h1T + 128 * HT_STRIDE;      // 64
    float* sps = sd2 + 64;                   // 4
    int*   snn = (int*)(sps + 4);            // 64

    const int b = blockIdx.y, m = blockIdx.x, tid = threadIdx.x;
    const int tx = tid & 31, ty = tid >> 5;
    const int bm = b * Mm + m;

    if (tid < NB) {
        snn[tid] = g_nn_idx[bm * NB + tid];
        sd2[tid] = g_nn_d2 [bm * NB + tid];
    }
    if (tid < 3) sps[tid] = pos_s[bm * 3 + tid];
    __syncthreads();

    // gather features (transposed): hT[c][k]
    for (int t = tid; t < NB * Cc; t += 256) {
        int k = t >> 6, c = t & 63;
        hT[c * HT_STRIDE + k] = x[((size_t)(b * Pp) + snn[k]) * Cc + c];
    }
    // relative positions: hT[64+d][k]
    for (int t = tid; t < NB * 3; t += 256) {
        int k = t / 3, d = t - 3 * k;
        hT[(64 + d) * HT_STRIDE + k] =
            __fsub_rn(pos[((size_t)(b * Pp) + snn[k]) * 3 + d], sps[d]);
    }
    __syncthreads();

    const float R2A = (float)(0.2 * 0.2);
    const float R2B = (float)(0.4 * 0.4);

    float* outrow = out + (size_t)bm * OUTC;
    // branch 2: K=64, 67->128->256, output channels [128,384)
    run_branch<64, 128, 256>(hT, h1T, sd2, w2_0, b2_0, w2_1, b2_1,
                             outrow + 128, R2B, tx, ty, tid);
    // branch 1: K=32 (prefix of sorted 64-NN), 67->64->128, channels [0,128)
    run_branch<32, 64, 128>(hT, h1T, sd2, w1_0, b1_0, w1_1, b1_1,
                            outrow, R2A, tx, ty, tid);
}

// ---------------------------------------------------------------------------
// launch
// ---------------------------------------------------------------------------
extern "C" void kernel_launch(void* const* d_in, const int* in_sizes, int n_in,
                              void* d_out, int out_size)
{
    const float* x    = (const float*)d_in[0];
    const float* pos  = (const float*)d_in[1];
    const float* w1_0 = (const float*)d_in[2];
    const float* b1_0 = (const float*)d_in[3];
    const float* w1_1 = (const float*)d_in[4];
    const float* b1_1 = (const float*)d_in[5];
    const float* w2_0 = (const float*)d_in[6];
    const float* b2_0 = (const float*)d_in[7];
    const float* w2_1 = (const float*)d_in[8];
    const float* b2_1 = (const float*)d_in[9];

    float* out   = (float*)d_out;
    float* pos_s = out + (size_t)Bb * Mm * OUTC;   // [out | pos_s] layout

    const int mlp_smem = (67 * HT_STRIDE + 128 * HT_STRIDE + 64 + 4 + 64) * 4;
    cudaFuncSetAttribute(mlp_kernel, cudaFuncAttributeMaxDynamicSharedMemorySize, mlp_smem);

    fps_kernel<<<Bb, 1024>>>(pos, pos_s);

    dim3 g(Mm, Bb);
    knn_kernel<<<g, 128>>>(pos, pos_s);

    mlp_kernel<<<g, 256, mlp_smem>>>(x, pos, pos_s,
                                     w1_0, b1_0, w1_1, b1_1,
                                     w2_0, b2_0, w2_1, b2_1, out);
}

// round 9
// speedup vs baseline: 1.0382x; 1.0022x over previous
#include <cuda_runtime.h>
#include <math_constants.h>

#define Bb 4
#define Pp 8192
#define Cc 64
#define Mm 2048
#define NB 64
#define OUTC 384

// scratch (allocation-free rule: __device__ globals)
__device__ int   g_nn_idx[Bb*Mm*NB];
__device__ float g_nn_d2 [Bb*Mm*NB];

// ---------------- packed f32x2 helpers (bitwise == two scalar rn ops) -------
typedef unsigned long long u64;

__device__ __forceinline__ u64 pk2(float lo, float hi) {
    u64 r; asm("mov.b64 %0, {%1, %2};" : "=l"(r) : "f"(lo), "f"(hi)); return r;
}
__device__ __forceinline__ void upk2(float& lo, float& hi, u64 v) {
    asm("mov.b64 {%0, %1}, %2;" : "=f"(lo), "=f"(hi) : "l"(v));
}
__device__ __forceinline__ u64 add2(u64 a, u64 b) {
    u64 d; asm("add.rn.f32x2 %0, %1, %2;" : "=l"(d) : "l"(a), "l"(b)); return d;
}
__device__ __forceinline__ u64 mul2(u64 a, u64 b) {
    u64 d; asm("mul.rn.f32x2 %0, %1, %2;" : "=l"(d) : "l"(a), "l"(b)); return d;
}
__device__ __forceinline__ u64 fma2(u64 a, u64 b, u64 c) {
    u64 d; asm("fma.rn.f32x2 %0, %1, %2, %3;" : "=l"(d) : "l"(a), "l"(b), "l"(c)); return d;
}

// ---------------------------------------------------------------------------
// Kernel 1: farthest point sampling, one block per batch.
// Bitwise-identical selection to the JAX scan: ((dx*dx+dy*dy)+dz*dz) rn ops,
// no fma contraction; argmax ties -> lowest index.
// ---------------------------------------------------------------------------
__global__ void __launch_bounds__(1024) fps_kernel(const float* __restrict__ pos,
                                                   float* __restrict__ pos_s)
{
    const int b = blockIdx.x;
    const float* pb = pos + (size_t)b * Pp * 3;
    float* ps = pos_s + (size_t)b * Mm * 3;
    const int tid = threadIdx.x;
    const int lane = tid & 31, wrp = tid >> 5;

    u64 px2[4], py2[4], pz2[4];
    unsigned mind[8];
#pragma unroll
    for (int q = 0; q < 4; q++) {
        int p0 = tid + (2 * q) * 1024;
        int p1 = tid + (2 * q + 1) * 1024;
        px2[q] = pk2(pb[3 * p0],     pb[3 * p1]);
        py2[q] = pk2(pb[3 * p0 + 1], pb[3 * p1 + 1]);
        pz2[q] = pk2(pb[3 * p0 + 2], pb[3 * p1 + 2]);
    }
#pragma unroll
    for (int i = 0; i < 8; i++) mind[i] = __float_as_uint(1e30f);

    __shared__ unsigned swv[2][32];
    __shared__ unsigned swi[2][32];

    unsigned sel = 0;
    for (int t = 0; t < Mm; t++) {
        float lx = pb[3 * sel], ly = pb[3 * sel + 1], lz = pb[3 * sel + 2];
        if (tid == 0) { ps[3 * t] = lx; ps[3 * t + 1] = ly; ps[3 * t + 2] = lz; }

        u64 nx2 = pk2(-lx, -lx);
        u64 ny2 = pk2(-ly, -ly);
        u64 nz2 = pk2(-lz, -lz);

#pragma unroll
        for (int q = 0; q < 4; q++) {
            u64 dx = add2(px2[q], nx2);
            u64 dy = add2(py2[q], ny2);
            u64 dz = add2(pz2[q], nz2);
            u64 s  = add2(add2(mul2(dx, dx), mul2(dy, dy)), mul2(dz, dz));
            float dlo, dhi;
            upk2(dlo, dhi, s);
            mind[2 * q]     = min(mind[2 * q],     __float_as_uint(dlo));
            mind[2 * q + 1] = min(mind[2 * q + 1], __float_as_uint(dhi));
        }
        // 7-op max tree (d2 >= 0 -> uint order == float order)
        unsigned m01 = max(mind[0], mind[1]), m23 = max(mind[2], mind[3]);
        unsigned m45 = max(mind[4], mind[5]), m67 = max(mind[6], mind[7]);
        unsigned bv  = max(max(m01, m23), max(m45, m67));

        // warp argmax (value first, then lowest point index among matches)
        unsigned wv = __reduce_max_sync(0xffffffffu, bv);
        unsigned cand = 0xffffffffu;
        if (bv == wv) {
#pragma unroll
            for (int i = 7; i >= 0; i--)
                if (mind[i] == wv) cand = (unsigned)(tid + (i << 10));
        }
        unsigned wi = __reduce_min_sync(0xffffffffu, cand);

        const int buf = t & 1;
        if (lane == 0) { swv[buf][wrp] = wv; swi[buf][wrp] = wi; }
        __syncthreads();

        // every warp resolves the block winner itself (no 2nd barrier)
        unsigned v  = swv[buf][lane];
        unsigned ii = swi[buf][lane];
        unsigned gv = __reduce_max_sync(0xffffffffu, v);
        unsigned c2 = (v == gv) ? ii : 0xffffffffu;
        sel = __reduce_min_sync(0xffffffffu, c2);
    }
}

// ---------------------------------------------------------------------------
// Kernel 2: 64 nearest neighbors per centroid, sorted ascending (tie: lower
// index). One block (128 thr) per centroid.
// ---------------------------------------------------------------------------
__global__ void __launch_bounds__(128) knn_kernel(const float* __restrict__ pos,
                                                  const float* __restrict__ pos_s)
{
    __shared__ float sd[Pp];           // 32 KB
    const int b = blockIdx.y, m = blockIdx.x, tid = threadIdx.x;
    const int bm = b * Mm + m;
    const float* pb = pos + (size_t)b * Pp * 3;
    const float cx = pos_s[bm * 3], cy = pos_s[bm * 3 + 1], cz = pos_s[bm * 3 + 2];

#pragma unroll 4
    for (int i = 0; i < 64; i++) {
        int p = tid + i * 128;
        float dx = __fsub_rn(cx, pb[3 * p]);
        float dy = __fsub_rn(cy, pb[3 * p + 1]);
        float dz = __fsub_rn(cz, pb[3 * p + 2]);
        sd[p] = __fadd_rn(__fadd_rn(__fmul_rn(dx, dx), __fmul_rn(dy, dy)),
                          __fmul_rn(dz, dz));
    }
    __syncthreads();

    unsigned lv = 0x7f800000u;   // +inf bits
    unsigned li = 0xffffffffu;
#pragma unroll 4
    for (int i = 0; i < 64; i++) {
        int p = tid + i * 128;
        unsigned v = __float_as_uint(sd[p]);   // d2 >= 0 -> bit order == numeric
        if (v < lv) { lv = v; li = (unsigned)p; }
    }

    __shared__ unsigned swv[4];
    __shared__ unsigned swi[4];
    __shared__ unsigned sgi;

    const unsigned wid = tid >> 5;

    for (int r = 0; r < NB; r++) {
        unsigned wv = __reduce_min_sync(0xffffffffu, lv);
        unsigned cand = (lv == wv) ? li : 0xffffffffu;
        unsigned wi = __reduce_min_sync(0xffffffffu, cand);
        if ((tid & 31) == 0) { swv[wid] = wv; swi[wid] = wi; }
        __syncthreads();
        if (tid == 0) {
            unsigned gv = swv[0], gi = swi[0];
#pragma unroll
            for (int w = 1; w < 4; w++)
                if (swv[w] < gv || (swv[w] == gv && swi[w] < gi)) { gv = swv[w]; gi = swi[w]; }
            sgi = gi;
            g_nn_idx[bm * NB + r] = (int)gi;
            g_nn_d2 [bm * NB + r] = __uint_as_float(gv);
        }
        __syncthreads();
        unsigned sel = sgi;
        unsigned ot = sel & 127u;          // owner thread within block
        if (wid == (ot >> 5)) {            // owner warp: cooperative rescan
            if (tid == (int)ot) sd[sel] = CUDART_INF_F;
            __syncwarp();
            int ln = tid & 31;
            unsigned v0 = __float_as_uint(sd[ot + (unsigned)(2 * ln) * 128u]);
            unsigned v1 = __float_as_uint(sd[ot + (unsigned)(2 * ln + 1) * 128u]);
            unsigned mv = min(v0, v1);
            unsigned mi = (v0 <= v1) ? (ot + (unsigned)(2 * ln) * 128u)
                                     : (ot + (unsigned)(2 * ln + 1) * 128u);
            unsigned rv = __reduce_min_sync(0xffffffffu, mv);
            unsigned rc = (mv == rv) ? mi : 0xffffffffu;
            unsigned ri = __reduce_min_sync(0xffffffffu, rc);
            if (tid == (int)ot) { lv = rv; li = ri; }
        }
    }
}

// ---------------------------------------------------------------------------
// Kernel 3: per-centroid MLP, packed f32x2 FMAs, k-loops unrolled x2 with
// front-batched weight LDGs (explicit software pipelining).
// Block 256 = (tx 32, ty 8).
// ---------------------------------------------------------------------------
#define HT_STRIDE 68

template<int K, int H1, int H2>
__device__ __forceinline__ void run_branch(
    const float* __restrict__ hT, float* __restrict__ h1T,
    const float* __restrict__ sd2,
    const float* __restrict__ W1, const float* __restrict__ B1b,
    const float* __restrict__ W2, const float* __restrict__ B2b,
    float* __restrict__ outrow, float r2, int tx, int ty, int tid)
{
    constexpr int KV = K / 8;     // neighbors per thread
    constexpr int IU = H1 / 32;   // hidden1 channels per thread
    constexpr int JU = H2 / 32;   // hidden2 channels per thread
    constexpr int IU2 = IU / 2, JU2 = JU / 2;
    constexpr bool SPLIT = (JU == 8);   // split channel halves for 16B/lane LDG

    // ---- GEMM1: h1[i][k] = relu(sum_c hT[c][k]*W1[c][i] + b1[i]) ----
    // c-loop unrolled x2 (66 rows paired + tail row 66); weight loads for both
    // sub-iterations issued up front.
    {
        u64 acc[KV][IU2];
#pragma unroll
        for (int v = 0; v < KV; v++)
#pragma unroll
            for (int u = 0; u < IU2; u++) acc[v][u] = 0ull;

        auto lda = [&](float* a, int c) {
            const float4* hp = (const float4*)(hT + c * HT_STRIDE + ty * KV);
#pragma unroll
            for (int q = 0; q < KV / 4; q++) {
                float4 t4 = hp[q];
                a[4*q] = t4.x; a[4*q+1] = t4.y; a[4*q+2] = t4.z; a[4*q+3] = t4.w;
            }
        };
        auto ldw = [&](u64* bb, int c) {
            const float* wp = W1 + c * H1 + tx * IU;
            if constexpr (IU == 4) {
                float4 t4 = *(const float4*)wp;
                bb[0] = pk2(t4.x, t4.y); bb[1] = pk2(t4.z, t4.w);
            } else {
                float2 t2 = *(const float2*)wp;
                bb[0] = pk2(t2.x, t2.y);
            }
        };
        auto body = [&](const float* a, const u64* bb) {
#pragma unroll
            for (int v = 0; v < KV; v++) {
                u64 av = pk2(a[v], a[v]);
#pragma unroll
                for (int u = 0; u < IU2; u++)
                    acc[v][u] = fma2(av, bb[u], acc[v][u]);
            }
        };

        for (int c = 0; c < 66; c += 2) {
            u64 bb0[IU2], bb1[IU2];
            float a0[KV], a1[KV];
            ldw(bb0, c); ldw(bb1, c + 1);        // batched LDGs first
            lda(a0, c);  lda(a1, c + 1);
            body(a0, bb0);
            body(a1, bb1);
        }
        {   // tail c = 66
            u64 bbt[IU2]; float at[KV];
            ldw(bbt, 66); lda(at, 66);
            body(at, bbt);
        }

        float bias[IU];
#pragma unroll
        for (int u = 0; u < IU; u++) bias[u] = B1b[tx * IU + u];
#pragma unroll
        for (int u = 0; u < IU2; u++) {
#pragma unroll
            for (int v = 0; v < KV; v++) {
                float lo, hi;
                upk2(lo, hi, acc[v][u]);
                int i0 = tx * IU + 2 * u;
                int k  = ty * KV + v;
                h1T[i0 * HT_STRIDE + k]       = fmaxf(lo + bias[2*u],     0.f);
                h1T[(i0 + 1) * HT_STRIDE + k] = fmaxf(hi + bias[2*u + 1], 0.f);
            }
        }
    }
    __syncthreads();

    // ---- GEMM2 + masked max over k ----
    // Channel mapping per thread:
    //   SPLIT (JU=8):  u<4 -> tx*4+u ; u>=4 -> H2/2 + tx*4 + (u-4)
    //   else  (JU=4):  u   -> tx*4+u
    // i-loop unrolled x2 (H1 even), weight LDGs for both iterations batched.
    {
        u64 acc[KV][JU2];
#pragma unroll
        for (int v = 0; v < KV; v++)
#pragma unroll
            for (int u = 0; u < JU2; u++) acc[v][u] = 0ull;

        auto ldw2 = [&](u64* bb, int i) {
            if constexpr (SPLIT) {
                float4 tA = *(const float4*)(W2 + i * H2 + tx * 4);
                float4 tB = *(const float4*)(W2 + i * H2 + H2 / 2 + tx * 4);
                bb[0] = pk2(tA.x, tA.y); bb[1] = pk2(tA.z, tA.w);
                bb[2] = pk2(tB.x, tB.y); bb[3] = pk2(tB.z, tB.w);
            } else {
                float4 t4 = *(const float4*)(W2 + i * H2 + tx * 4);
                bb[0] = pk2(t4.x, t4.y); bb[1] = pk2(t4.z, t4.w);
            }
        };
        auto lda2 = [&](float* a, int i) {
            const float4* hp = (const float4*)(h1T + i * HT_STRIDE + ty * KV);
#pragma unroll
            for (int q = 0; q < KV / 4; q++) {
                float4 t4 = hp[q];
                a[4*q] = t4.x; a[4*q+1] = t4.y; a[4*q+2] = t4.z; a[4*q+3] = t4.w;
            }
        };
        auto body2 = [&](const float* a, const u64* bb) {
#pragma unroll
            for (int v = 0; v < KV; v++) {
                u64 av = pk2(a[v], a[v]);
#pragma unroll
                for (int u = 0; u < JU2; u++)
                    acc[v][u] = fma2(av, bb[u], acc[v][u]);
            }
        };

        for (int i = 0; i < H1; i += 2) {
            u64 bb0[JU2], bb1[JU2];
            float a0[KV], a1[KV];
            ldw2(bb0, i); ldw2(bb1, i + 1);      // batched LDGs first
            lda2(a0, i);  lda2(a1, i + 1);
            body2(a0, bb0);
            body2(a1, bb1);
        }

        // channel index for mx[u]
        auto CH = [&](int u) -> int {
            if constexpr (SPLIT) return (u < 4) ? (tx * 4 + u) : (H2 / 2 + tx * 4 + (u - 4));
            else                 return tx * 4 + u;
        };

        float b2[JU];
#pragma unroll
        for (int u = 0; u < JU; u++) b2[u] = B2b[CH(u)];
        float mx[JU];
#pragma unroll
        for (int u = 0; u < JU; u++) mx[u] = -1e30f;
#pragma unroll
        for (int v = 0; v < KV; v++) {
            bool ok = (sd2[ty * KV + v] <= r2);
#pragma unroll
            for (int u = 0; u < JU2; u++) {
                float lo, hi;
                upk2(lo, hi, acc[v][u]);
                float v0 = fmaxf(lo + b2[2*u],     0.f);
                float v1 = fmaxf(hi + b2[2*u + 1], 0.f);
                if (!ok) { v0 = -1e30f; v1 = -1e30f; }
                mx[2*u]     = fmaxf(mx[2*u],     v0);
                mx[2*u + 1] = fmaxf(mx[2*u + 1], v1);
            }
        }

        // red aliases h1T: all h1T reads are done (acc complete), sync then reuse
        __syncthreads();
        float* red = h1T;   // 8 * H2 <= 2048 floats, fits in h1T region
#pragma unroll
        for (int u = 0; u < JU; u++) red[ty * H2 + CH(u)] = mx[u];
        __syncthreads();
        for (int j = tid; j < H2; j += 256) {
            float mm = red[j];
#pragma unroll
            for (int w = 1; w < 8; w++) mm = fmaxf(mm, red[w * H2 + j]);
            outrow[j] = mm;
        }
        __syncthreads();
    }
}

__global__ void __launch_bounds__(256, 2) mlp_kernel(
    const float* __restrict__ x, const float* __restrict__ pos,
    const float* __restrict__ pos_s,
    const float* __restrict__ w1_0, const float* __restrict__ b1_0,
    const float* __restrict__ w1_1, const float* __restrict__ b1_1,
    const float* __restrict__ w2_0, const float* __restrict__ b2_0,
    const float* __restrict__ w2_1, const float* __restrict__ b2_1,
    float* __restrict__ out)
{
    extern __shared__ float sm[];
    float* hT  = sm;                         // 67 * 68 = 4556 floats
    float* h1T = hT + 67 * HT_STRIDE;        // 128 * 68 = 8704 floats (also red)
    float* sd2 = h1T + 128 * HT_STRIDE;      // 64
    float* sps = sd2 + 64;                   // 4
    int*   snn = (int*)(sps + 4);            // 64

    const int b = blockIdx.y, m = blockIdx.x, tid = threadIdx.x;
    const int tx = tid & 31, ty = tid >> 5;
    const int bm = b * Mm + m;

    if (tid < NB) {
        snn[tid] = g_nn_idx[bm * NB + tid];
        sd2[tid] = g_nn_d2 [bm * NB + tid];
    }
    if (tid < 3) sps[tid] = pos_s[bm * 3 + tid];
    __syncthreads();

    // gather features (transposed): hT[c][k], float4 global loads
    // t indexes (k, c4): each thread moves 4 consecutive channels of one row
    for (int t = tid; t < NB * (Cc / 4); t += 256) {
        int k = t >> 4, c4 = t & 15;
        float4 v4 = *(const float4*)(x + ((size_t)(b * Pp) + snn[k]) * Cc + c4 * 4);
        int c = c4 * 4;
        hT[(c + 0) * HT_STRIDE + k] = v4.x;
        hT[(c + 1) * HT_STRIDE + k] = v4.y;
        hT[(c + 2) * HT_STRIDE + k] = v4.z;
        hT[(c + 3) * HT_STRIDE + k] = v4.w;
    }
    // relative positions: hT[64+d][k]
    for (int t = tid; t < NB * 3; t += 256) {
        int k = t / 3, d = t - 3 * k;
        hT[(64 + d) * HT_STRIDE + k] =
            __fsub_rn(pos[((size_t)(b * Pp) + snn[k]) * 3 + d], sps[d]);
    }
    __syncthreads();

    const float R2A = (float)(0.2 * 0.2);
    const float R2B = (float)(0.4 * 0.4);

    float* outrow = out + (size_t)bm * OUTC;
    // branch 2: K=64, 67->128->256, output channels [128,384)
    run_branch<64, 128, 256>(hT, h1T, sd2, w2_0, b2_0, w2_1, b2_1,
                             outrow + 128, R2B, tx, ty, tid);
    // branch 1: K=32 (prefix of sorted 64-NN), 67->64->128, channels [0,128)
    run_branch<32, 64, 128>(hT, h1T, sd2, w1_0, b1_0, w1_1, b1_1,
                            outrow, R2A, tx, ty, tid);
}

// ---------------------------------------------------------------------------
// launch
// ---------------------------------------------------------------------------
extern "C" void kernel_launch(void* const* d_in, const int* in_sizes, int n_in,
                              void* d_out, int out_size)
{
    const float* x    = (const float*)d_in[0];
    const float* pos  = (const float*)d_in[1];
    const float* w1_0 = (const float*)d_in[2];
    const float* b1_0 = (const float*)d_in[3];
    const float* w1_1 = (const float*)d_in[4];
    const float* b1_1 = (const float*)d_in[5];
    const float* w2_0 = (const float*)d_in[6];
    const float* b2_0 = (const float*)d_in[7];
    const float* w2_1 = (const float*)d_in[8];
    const float* b2_1 = (const float*)d_in[9];

    float* out   = (float*)d_out;
    float* pos_s = out + (size_t)Bb * Mm * OUTC;   // [out | pos_s] layout

    const int mlp_smem = (67 * HT_STRIDE + 128 * HT_STRIDE + 64 + 4 + 64) * 4;
    cudaFuncSetAttribute(mlp_kernel, cudaFuncAttributeMaxDynamicSharedMemorySize, mlp_smem);

    fps_kernel<<<Bb, 1024>>>(pos, pos_s);

    dim3 g(Mm, Bb);
    knn_kernel<<<g, 128>>>(pos, pos_s);

    mlp_kernel<<<g, 256, mlp_smem>>>(x, pos, pos_s,
                                     w1_0, b1_0, w1_1, b1_1,
                                     w2_0, b2_0, w2_1, b2_1, out);
}

// round 10
// speedup vs baseline: 1.3522x; 1.3024x over previous
#include <cuda_runtime.h>
#include <math_constants.h>

#define Bb 4
#define Pp 8192
#define Cc 64
#define Mm 2048
#define NB 64
#define OUTC 384
#define HT_STRIDE 68

// per-wg smem floats: union(hT 67*68 + h1T 128*68 = 13260; sd needs 8192) -> 13264 pad
// + sd2 64 + snn 64 + swv/swi 32  -> 13424 -> pad 13440
#define WGF 13440

__device__ unsigned g_progress[Bb];

// ---------------- packed f32x2 helpers (bitwise == two scalar rn ops) -------
typedef unsigned long long u64;

__device__ __forceinline__ u64 pk2(float lo, float hi) {
    u64 r; asm("mov.b64 %0, {%1, %2};" : "=l"(r) : "f"(lo), "f"(hi)); return r;
}
__device__ __forceinline__ void upk2(float& lo, float& hi, u64 v) {
    asm("mov.b64 {%0, %1}, %2;" : "=f"(lo), "=f"(hi) : "l"(v));
}
__device__ __forceinline__ u64 add2(u64 a, u64 b) {
    u64 d; asm("add.rn.f32x2 %0, %1, %2;" : "=l"(d) : "l"(a), "l"(b)); return d;
}
__device__ __forceinline__ u64 mul2(u64 a, u64 b) {
    u64 d; asm("mul.rn.f32x2 %0, %1, %2;" : "=l"(d) : "l"(a), "l"(b)); return d;
}
__device__ __forceinline__ u64 fma2(u64 a, u64 b, u64 c) {
    u64 d; asm("fma.rn.f32x2 %0, %1, %2, %3;" : "=l"(d) : "l"(a), "l"(b), "l"(c)); return d;
}
__device__ __forceinline__ unsigned ld_acq(const unsigned* p) {
    unsigned v; asm volatile("ld.acquire.gpu.global.u32 %0, [%1];" : "=r"(v) : "l"(p)); return v;
}
__device__ __forceinline__ void st_rel(unsigned* p, unsigned v) {
    asm volatile("st.release.gpu.global.u32 [%0], %1;" :: "l"(p), "r"(v) : "memory");
}
__device__ __forceinline__ void wgbar(int id) {
    asm volatile("bar.sync %0, 256;" :: "r"(id) : "memory");
}

// ---------------------------------------------------------------------------
// FPS for one batch, 512 threads (16 points/thread). Bitwise-identical
// selection to the JAX scan. Publishes progress[b] = t+1 after writing ps[t].
// ---------------------------------------------------------------------------
__device__ void fps_block(int b, const float* __restrict__ pos,
                          float* __restrict__ pos_s, unsigned* __restrict__ smu)
{
    const float* pb = pos + (size_t)b * Pp * 3;
    float* ps = pos_s + (size_t)b * Mm * 3;
    const int tid = threadIdx.x;
    const int lane = tid & 31, wrp = tid >> 5;     // 16 warps

    u64 px2[8], py2[8], pz2[8];
    unsigned mind[16];
#pragma unroll
    for (int q = 0; q < 8; q++) {
        int p0 = tid + (2 * q) * 512;
        int p1 = p0 + 512;
        px2[q] = pk2(pb[3 * p0],     pb[3 * p1]);
        py2[q] = pk2(pb[3 * p0 + 1], pb[3 * p1 + 1]);
        pz2[q] = pk2(pb[3 * p0 + 2], pb[3 * p1 + 2]);
    }
#pragma unroll
    for (int i = 0; i < 16; i++) mind[i] = __float_as_uint(1e30f);

    unsigned* swv = smu;         // [2][16]
    unsigned* swi = smu + 32;    // [2][16]

    unsigned sel = 0;
    for (int t = 0; t < Mm; t++) {
        float lx = pb[3 * sel], ly = pb[3 * sel + 1], lz = pb[3 * sel + 2];
        if (tid == 0) {
            ps[3 * t] = lx; ps[3 * t + 1] = ly; ps[3 * t + 2] = lz;
            st_rel(&g_progress[b], (unsigned)(t + 1));
        }

        u64 nx2 = pk2(-lx, -lx);
        u64 ny2 = pk2(-ly, -ly);
        u64 nz2 = pk2(-lz, -lz);

#pragma unroll
        for (int q = 0; q < 8; q++) {
            u64 dx = add2(px2[q], nx2);
            u64 dy = add2(py2[q], ny2);
            u64 dz = add2(pz2[q], nz2);
            u64 s  = add2(add2(mul2(dx, dx), mul2(dy, dy)), mul2(dz, dz));
            float dlo, dhi;
            upk2(dlo, dhi, s);
            mind[2 * q]     = min(mind[2 * q],     __float_as_uint(dlo));
            mind[2 * q + 1] = min(mind[2 * q + 1], __float_as_uint(dhi));
        }
        // 15-op max tree (d2 >= 0 -> uint order == float order)
        unsigned bv;
        {
            unsigned a0 = max(mind[0], mind[1]),  a1 = max(mind[2], mind[3]);
            unsigned a2 = max(mind[4], mind[5]),  a3 = max(mind[6], mind[7]);
            unsigned a4 = max(mind[8], mind[9]),  a5 = max(mind[10], mind[11]);
            unsigned a6 = max(mind[12], mind[13]), a7 = max(mind[14], mind[15]);
            unsigned b0 = max(a0, a1), b1 = max(a2, a3), b2 = max(a4, a5), b3 = max(a6, a7);
            bv = max(max(b0, b1), max(b2, b3));
        }

        unsigned wv = __reduce_max_sync(0xffffffffu, bv);
        unsigned cand = 0xffffffffu;
        if (bv == wv) {
#pragma unroll
            for (int i = 15; i >= 0; i--)
                if (mind[i] == wv) cand = (unsigned)(tid + (i << 9));
        }
        unsigned wi = __reduce_min_sync(0xffffffffu, cand);

        const int buf = (t & 1) * 16;
        if (lane == 0) { swv[buf + wrp] = wv; swi[buf + wrp] = wi; }
        __syncthreads();

        unsigned v  = (lane < 16) ? swv[buf + lane] : 0u;
        unsigned ii = (lane < 16) ? swi[buf + lane] : 0xffffffffu;
        unsigned gv = __reduce_max_sync(0xffffffffu, v);
        unsigned c2 = (v == gv && lane < 16) ? ii : 0xffffffffu;
        sel = __reduce_min_sync(0xffffffffu, c2);
    }
}

// ---------------------------------------------------------------------------
// per-centroid MLP branch (256-thread sub-unit, named barrier `barid`).
// Packed f32x2 FMAs; GEMM2 weight LDGs use 16B/lane strides.
// ---------------------------------------------------------------------------
template<int K, int H1, int H2>
__device__ __forceinline__ void run_branch(
    const float* __restrict__ hT, float* __restrict__ h1T,
    const float* __restrict__ sd2,
    const float* __restrict__ W1, const float* __restrict__ B1b,
    const float* __restrict__ W2, const float* __restrict__ B2b,
    float* __restrict__ outrow, float r2, int tx, int ty, int t, int barid)
{
    constexpr int KV = K / 8;
    constexpr int IU = H1 / 32;
    constexpr int JU = H2 / 32;
    constexpr int IU2 = IU / 2, JU2 = JU / 2;
    constexpr bool SPLIT = (JU == 8);

    // ---- GEMM1 ----
    {
        u64 acc[KV][IU2];
#pragma unroll
        for (int v = 0; v < KV; v++)
#pragma unroll
            for (int u = 0; u < IU2; u++) acc[v][u] = 0ull;

        auto lda = [&](float* a, int c) {
            const float4* hp = (const float4*)(hT + c * HT_STRIDE + ty * KV);
#pragma unroll
            for (int q = 0; q < KV / 4; q++) {
                float4 t4 = hp[q];
                a[4*q] = t4.x; a[4*q+1] = t4.y; a[4*q+2] = t4.z; a[4*q+3] = t4.w;
            }
        };
        auto ldw = [&](u64* bb, int c) {
            const float* wp = W1 + c * H1 + tx * IU;
            if constexpr (IU == 4) {
                float4 t4 = *(const float4*)wp;
                bb[0] = pk2(t4.x, t4.y); bb[1] = pk2(t4.z, t4.w);
            } else {
                float2 t2 = *(const float2*)wp;
                bb[0] = pk2(t2.x, t2.y);
            }
        };
        auto body = [&](const float* a, const u64* bb) {
#pragma unroll
            for (int v = 0; v < KV; v++) {
                u64 av = pk2(a[v], a[v]);
#pragma unroll
                for (int u = 0; u < IU2; u++)
                    acc[v][u] = fma2(av, bb[u], acc[v][u]);
            }
        };

        for (int c = 0; c < 66; c += 2) {
            u64 bb0[IU2], bb1[IU2];
            float a0[KV], a1[KV];
            ldw(bb0, c); ldw(bb1, c + 1);
            lda(a0, c);  lda(a1, c + 1);
            body(a0, bb0);
            body(a1, bb1);
        }
        {
            u64 bbt[IU2]; float at[KV];
            ldw(bbt, 66); lda(at, 66);
            body(at, bbt);
        }

        float bias[IU];
#pragma unroll
        for (int u = 0; u < IU; u++) bias[u] = B1b[tx * IU + u];
#pragma unroll
        for (int u = 0; u < IU2; u++) {
#pragma unroll
            for (int v = 0; v < KV; v++) {
                float lo, hi;
                upk2(lo, hi, acc[v][u]);
                int i0 = tx * IU + 2 * u;
                int k  = ty * KV + v;
                h1T[i0 * HT_STRIDE + k]       = fmaxf(lo + bias[2*u],     0.f);
                h1T[(i0 + 1) * HT_STRIDE + k] = fmaxf(hi + bias[2*u + 1], 0.f);
            }
        }
    }
    wgbar(barid);

    // ---- GEMM2 + masked max ----
    {
        u64 acc[KV][JU2];
#pragma unroll
        for (int v = 0; v < KV; v++)
#pragma unroll
            for (int u = 0; u < JU2; u++) acc[v][u] = 0ull;

        auto ldw2 = [&](u64* bb, int i) {
            if constexpr (SPLIT) {
                float4 tA = *(const float4*)(W2 + i * H2 + tx * 4);
                float4 tB = *(const float4*)(W2 + i * H2 + H2 / 2 + tx * 4);
                bb[0] = pk2(tA.x, tA.y); bb[1] = pk2(tA.z, tA.w);
                bb[2] = pk2(tB.x, tB.y); bb[3] = pk2(tB.z, tB.w);
            } else {
                float4 t4 = *(const float4*)(W2 + i * H2 + tx * 4);
                bb[0] = pk2(t4.x, t4.y); bb[1] = pk2(t4.z, t4.w);
            }
        };
        auto lda2 = [&](float* a, int i) {
            const float4* hp = (const float4*)(h1T + i * HT_STRIDE + ty * KV);
#pragma unroll
            for (int q = 0; q < KV / 4; q++) {
                float4 t4 = hp[q];
                a[4*q] = t4.x; a[4*q+1] = t4.y; a[4*q+2] = t4.z; a[4*q+3] = t4.w;
            }
        };
        auto body2 = [&](const float* a, const u64* bb) {
#pragma unroll
            for (int v = 0; v < KV; v++) {
                u64 av = pk2(a[v], a[v]);
#pragma unroll
                for (int u = 0; u < JU2; u++)
                    acc[v][u] = fma2(av, bb[u], acc[v][u]);
            }
        };

        for (int i = 0; i < H1; i += 2) {
            u64 bb0[JU2], bb1[JU2];
            float a0[KV], a1[KV];
            ldw2(bb0, i); ldw2(bb1, i + 1);
            lda2(a0, i);  lda2(a1, i + 1);
            body2(a0, bb0);
            body2(a1, bb1);
        }

        auto CH = [&](int u) -> int {
            if constexpr (SPLIT) return (u < 4) ? (tx * 4 + u) : (H2 / 2 + tx * 4 + (u - 4));
            else                 return tx * 4 + u;
        };

        float b2[JU];
#pragma unroll
        for (int u = 0; u < JU; u++) b2[u] = B2b[CH(u)];
        float mx[JU];
#pragma unroll
        for (int u = 0; u < JU; u++) mx[u] = -1e30f;
#pragma unroll
        for (int v = 0; v < KV; v++) {
            bool ok = (sd2[ty * KV + v] <= r2);
#pragma unroll
            for (int u = 0; u < JU2; u++) {
                float lo, hi;
                upk2(lo, hi, acc[v][u]);
                float v0 = fmaxf(lo + b2[2*u],     0.f);
                float v1 = fmaxf(hi + b2[2*u + 1], 0.f);
                if (!ok) { v0 = -1e30f; v1 = -1e30f; }
                mx[2*u]     = fmaxf(mx[2*u],     v0);
                mx[2*u + 1] = fmaxf(mx[2*u + 1], v1);
            }
        }

        wgbar(barid);
        float* red = h1T;   // 8 * H2 <= 2048 floats, fits in h1T region
#pragma unroll
        for (int u = 0; u < JU; u++) red[ty * H2 + CH(u)] = mx[u];
        wgbar(barid);
        for (int j = t; j < H2; j += 256) {
            float mm = red[j];
#pragma unroll
            for (int w = 1; w < 8; w++) mm = fmaxf(mm, red[w * H2 + j]);
            outrow[j] = mm;
        }
        wgbar(barid);
    }
}

// ---------------------------------------------------------------------------
// Fused kernel: blocks 0..3 = FPS; blocks 4.. = workers (2 sub-units x 256thr,
// each doing KNN + MLP for one centroid, spin-waiting on FPS progress).
// ---------------------------------------------------------------------------
__global__ void __launch_bounds__(512, 1) fused_kernel(
    const float* __restrict__ x, const float* __restrict__ pos,
    const float* __restrict__ w1_0, const float* __restrict__ b1_0,
    const float* __restrict__ w1_1, const float* __restrict__ b1_1,
    const float* __restrict__ w2_0, const float* __restrict__ b2_0,
    const float* __restrict__ w2_1, const float* __restrict__ b2_1,
    float* __restrict__ out, float* __restrict__ pos_s)
{
    extern __shared__ float sm[];

    if (blockIdx.x < Bb) {
        fps_block(blockIdx.x, pos, pos_s, (unsigned*)sm);
        return;
    }

    const int w  = blockIdx.x - Bb;
    const int wg = threadIdx.x >> 8;          // 0..1
    const int t  = threadIdx.x & 255;
    const int barid = wg + 1;
    const int b  = 2 * (w & 1) + wg;
    const int m  = w >> 1;
    const int bm = b * Mm + m;
    const int lane = t & 31, w8 = t >> 5;

    float*    base = sm + wg * WGF;
    float*    un   = base;                    // union: sd[8192] / hT+h1T[13260]
    float*    sd2s = base + 13264;            // 64
    int*      snn  = (int*)(base + 13328);    // 64
    unsigned* swv  = (unsigned*)(base + 13392);  // [2][8]
    unsigned* swi  = swv + 16;                   // [2][8]

    // ---- wait for our centroid ----
    if (t == 0) {
        while (ld_acq(&g_progress[b]) <= (unsigned)m) __nanosleep(128);
    }
    wgbar(barid);

    const float cx = pos_s[bm * 3], cy = pos_s[bm * 3 + 1], cz = pos_s[bm * 3 + 2];
    const float* pb = pos + (size_t)b * Pp * 3;

    // ---- KNN: distances (packed, bitwise == scalar rn) ----
    float* sd = un;
    unsigned lv = 0x7f800000u, li = 0xffffffffu;
    {
        u64 c2x = pk2(cx, cx), c2y = pk2(cy, cy), c2z = pk2(cz, cz);
        const u64 SMASK = 0x8000000080000000ull;
#pragma unroll 4
        for (int q = 0; q < 16; q++) {
            int p0 = t + (2 * q) * 256;
            int p1 = p0 + 256;
            u64 X = pk2(pb[3 * p0],     pb[3 * p1]);
            u64 Y = pk2(pb[3 * p0 + 1], pb[3 * p1 + 1]);
            u64 Z = pk2(pb[3 * p0 + 2], pb[3 * p1 + 2]);
            u64 dx = add2(c2x, X ^ SMASK);    // cx + (-px) == cx - px (rn exact)
            u64 dy = add2(c2y, Y ^ SMASK);
            u64 dz = add2(c2z, Z ^ SMASK);
            u64 s  = add2(add2(mul2(dx, dx), mul2(dy, dy)), mul2(dz, dz));
            float dlo, dhi;
            upk2(dlo, dhi, s);
            sd[p0] = dlo; sd[p1] = dhi;
            unsigned v0 = __float_as_uint(dlo), v1 = __float_as_uint(dhi);
            if (v0 < lv) { lv = v0; li = (unsigned)p0; }
            if (v1 < lv) { lv = v1; li = (unsigned)p1; }
        }
    }
    wgbar(barid);

    // ---- KNN: 64 rounds of block argmin (value, then lowest index) ----
    for (int r = 0; r < NB; r++) {
        unsigned wv = __reduce_min_sync(0xffffffffu, lv);
        unsigned cand = (lv == wv) ? li : 0xffffffffu;
        unsigned wi = __reduce_min_sync(0xffffffffu, cand);
        const int buf = (r & 1) * 8;
        if (lane == 0) { swv[buf + w8] = wv; swi[buf + w8] = wi; }
        wgbar(barid);
        unsigned v  = (lane < 8) ? swv[buf + lane] : 0xffffffffu;
        unsigned ii = (lane < 8) ? swi[buf + lane] : 0xffffffffu;
        unsigned gv = __reduce_min_sync(0xffffffffu, v);
        unsigned c2 = (v == gv && lane < 8) ? ii : 0xffffffffu;
        unsigned gi = __reduce_min_sync(0xffffffffu, c2);
        if (t == 0) { snn[r] = (int)gi; sd2s[r] = __uint_as_float(gv); }
        unsigned ot = gi & 255u;                 // owner thread in wg
        if ((unsigned)w8 == (ot >> 5)) {         // owner warp: cooperative rescan
            if ((unsigned)t == ot) sd[gi] = CUDART_INF_F;
            __syncwarp();
            unsigned pp = ot + (unsigned)lane * 256u;
            unsigned vv = __float_as_uint(sd[pp]);
            unsigned mv = __reduce_min_sync(0xffffffffu, vv);
            unsigned mc = (vv == mv) ? pp : 0xffffffffu;
            unsigned mi = __reduce_min_sync(0xffffffffu, mc);
            if ((unsigned)t == ot) { lv = mv; li = mi; }
        }
    }
    wgbar(barid);

    // ---- gather hT (overwrites sd region; all KNN reads done) ----
    float* hT  = un;
    float* h1T = un + 67 * HT_STRIDE;
    for (int t2 = t; t2 < NB * (Cc / 4); t2 += 256) {
        int k = t2 >> 4, c4 = t2 & 15;
        float4 v4 = *(const float4*)(x + ((size_t)(b * Pp) + snn[k]) * Cc + c4 * 4);
        int c = c4 * 4;
        hT[(c + 0) * HT_STRIDE + k] = v4.x;
        hT[(c + 1) * HT_STRIDE + k] = v4.y;
        hT[(c + 2) * HT_STRIDE + k] = v4.z;
        hT[(c + 3) * HT_STRIDE + k] = v4.w;
    }
    for (int t2 = t; t2 < NB * 3; t2 += 256) {
        int k = t2 / 3, d = t2 - 3 * k;
        float cd = (d == 0) ? cx : ((d == 1) ? cy : cz);
        hT[(64 + d) * HT_STRIDE + k] =
            __fsub_rn(pos[((size_t)(b * Pp) + snn[k]) * 3 + d], cd);
    }
    wgbar(barid);

    const float R2A = (float)(0.2 * 0.2);
    const float R2B = (float)(0.4 * 0.4);
    const int tx = t & 31, ty = t >> 5;

    float* outrow = out + (size_t)bm * OUTC;
    run_branch<64, 128, 256>(hT, h1T, sd2s, w2_0, b2_0, w2_1, b2_1,
                             outrow + 128, R2B, tx, ty, t, barid);
    run_branch<32, 64, 128>(hT, h1T, sd2s, w1_0, b1_0, w1_1, b1_1,
                            outrow, R2A, tx, ty, t, barid);
}

// ---------------------------------------------------------------------------
// launch
// ---------------------------------------------------------------------------
extern "C" void kernel_launch(void* const* d_in, const int* in_sizes, int n_in,
                              void* d_out, int out_size)
{
    const float* x    = (const float*)d_in[0];
    const float* pos  = (const float*)d_in[1];
    const float* w1_0 = (const float*)d_in[2];
    const float* b1_0 = (const float*)d_in[3];
    const float* w1_1 = (const float*)d_in[4];
    const float* b1_1 = (const float*)d_in[5];
    const float* w2_0 = (const float*)d_in[6];
    const float* b2_0 = (const float*)d_in[7];
    const float* w2_1 = (const float*)d_in[8];
    const float* b2_1 = (const float*)d_in[9];

    float* out   = (float*)d_out;
    float* pos_s = out + (size_t)Bb * Mm * OUTC;   // [out | pos_s] layout

    // reset progress counters every invocation (graph replay safe)
    void* paddr = nullptr;
    cudaGetSymbolAddress(&paddr, g_progress);
    cudaMemsetAsync(paddr, 0, sizeof(unsigned) * Bb);

    const int smem = 2 * WGF * 4;   // 107520 bytes
    cudaFuncSetAttribute(fused_kernel, cudaFuncAttributeMaxDynamicSharedMemorySize, smem);

    fused_kernel<<<Bb + 2 * Mm, 512, smem>>>(x, pos,
                                             w1_0, b1_0, w1_1, b1_1,
                                             w2_0, b2_0, w2_1, b2_1,
                                             out, pos_s);
}